// round 14
// baseline (speedup 1.0000x reference)
#include <cuda_runtime.h>
#include <cuda_fp16.h>
#include <math.h>
#include <stdint.h>

#define Bb 4096
#define Tt 32
#define Cc 180
#define Hh 6
#define HDd 30
#define Ff 720
#define EPS 1e-5f
#define ROWS (Bb*Tt)

#define QBLK  25600
#define W1BLK 25600
#define W2BLK 27648

// ============================================================================
// Device scratch
// ============================================================================
__device__ float g_X2[(size_t)ROWS * Cc];
__device__ __align__(16) char g_WQB[9  * QBLK];
__device__ __align__(16) char g_W1B[12 * W1BLK];
__device__ __align__(16) char g_W2B[12 * W2BLK];

// ============================================================================
// helpers
// ============================================================================
__device__ __forceinline__ unsigned smem_u32(const void* p) {
    unsigned a;
    asm("{ .reg .u64 t; cvta.to.shared.u64 t, %1; cvt.u32.u64 %0, t; }" : "=r"(a) : "l"(p));
    return a;
}
__device__ __forceinline__ void ldsm_x4(unsigned* r, unsigned addr) {
    asm volatile("ldmatrix.sync.aligned.m8n8.x4.shared.b16 {%0,%1,%2,%3}, [%4];"
                 : "=r"(r[0]), "=r"(r[1]), "=r"(r[2]), "=r"(r[3]) : "r"(addr));
}
__device__ __forceinline__ void mma16816(float* c, const unsigned* a, const unsigned* b) {
    asm volatile(
        "mma.sync.aligned.m16n8k16.row.col.f32.f16.f16.f32 "
        "{%0,%1,%2,%3}, {%4,%5,%6,%7}, {%8,%9}, {%0,%1,%2,%3};"
        : "+f"(c[0]), "+f"(c[1]), "+f"(c[2]), "+f"(c[3])
        : "r"(a[0]), "r"(a[1]), "r"(a[2]), "r"(a[3]), "r"(b[0]), "r"(b[1]));
}
__device__ __forceinline__ unsigned pack2h(float v0, float v1) {
    __half2 h = __halves2half2(__float2half_rn(v0), __float2half_rn(v1));
    return *reinterpret_cast<unsigned*>(&h);
}
#define MBAR_INIT(mb, c) \
    asm volatile("mbarrier.init.shared.b64 [%0], %1;" :: "r"((unsigned)(mb)), "r"((unsigned)(c)) : "memory")
#define MBAR_EXPECT_TX(mb, tx) \
    asm volatile("mbarrier.arrive.expect_tx.shared.b64 _, [%0], %1;" :: "r"((unsigned)(mb)), "r"((unsigned)(tx)) : "memory")
#define MBAR_WAIT(mb, par) do { \
    unsigned _m = (unsigned)(mb); unsigned _p = (unsigned)(par); unsigned _d; \
    asm volatile("{\n\t.reg .pred p;\n\t" \
        "mbarrier.try_wait.parity.acquire.cta.shared::cta.b64 p, [%1], %2;\n\t" \
        "selp.b32 %0, 1, 0, p;\n\t}" : "=r"(_d) : "r"(_m), "r"(_p) : "memory"); \
    if (!_d) { \
        asm volatile("{\n\t.reg .pred P1;\n\t" \
            "WL_%=:\n\t" \
            "mbarrier.try_wait.parity.acquire.cta.shared::cta.b64 P1, [%0], %1, 0x989680;\n\t" \
            "@P1 bra.uni WD_%=;\n\t" \
            "bra.uni WL_%=;\n\t" \
            "WD_%=:\n\t}" :: "r"(_m), "r"(_p) : "memory"); \
    } } while (0)
#define BULK_LD(dst, src, sz, mb) \
    asm volatile("cp.async.bulk.shared::cluster.global.mbarrier::complete_tx::bytes [%0], [%1], %2, [%3];" \
                 :: "r"((unsigned)(dst)), "l"(src), "r"((unsigned)(sz)), "r"((unsigned)(mb)) : "memory")

// ============================================================================
// Prep
// ============================================================================
__global__ void prep_all(const float* __restrict__ wq, const float* __restrict__ wk,
                         const float* __restrict__ wv, const float* __restrict__ w1,
                         const float* __restrict__ w2) {
    const int NWQ = 576 * 192, NW1 = 768 * 192, NW2 = 192 * 768;
    for (int i = blockIdx.x * blockDim.x + threadIdx.x; i < NWQ + NW1 + NW2;
         i += gridDim.x * blockDim.x) {
        float v = 0.f;
        char* p;
        if (i < NWQ) {
            int n = i / 192, k = i % 192;
            if (n < 540 && k < Cc) {
                int mat = n / Cc, m = n % Cc;
                int hh = m / HDd, d = m % HDd;
                const float* W = (mat == 0 ? wq : (mat == 1 ? wk : wv));
                v = W[(size_t)hh * (Cc*HDd) + (size_t)k * HDd + d];
            }
            p = g_WQB + (n >> 6) * QBLK + (n & 63) * 400 + k * 2;
        } else if (i < NWQ + NW1) {
            int j = i - NWQ;
            int n = j / 192, k = j % 192;
            if (n < Ff && k < Cc) v = w1[(size_t)k * Ff + n];
            p = g_W1B + (n >> 6) * W1BLK + (n & 63) * 400 + k * 2;
        } else {
            int j = i - NWQ - NW1;
            int n = j / 768, k = j % 768;
            if (n < Cc && k < Ff) v = w2[(size_t)k * Cc + n];
            p = g_W2B + (k >> 6) * W2BLK + n * 144 + (k & 63) * 2;
        }
        *(__half*)p = __float2half_rn(v);
    }
}

// ============================================================================
// Kernel 1 (fused): LN1 + QKV GEMM + softmax + A@V + residual -> g_X2
//   64 rows/CTA (= 2 batches), 256 threads, QKV kept in smem (f32).
// ============================================================================
#define NTK 256
#define QA1   0
#define QB0   25600
#define QB1   51200
#define QKVB  76800                 // f32 qkv: 64 rows x stride 588 f32
#define SQ    588                   // row stride (f32): 588 % 32 = 12 -> conflict-free
#define QBAR  (QKVB + 64*SQ*4)      // 227328
#define SMF_TOTAL (QBAR + 32)       // 227360 bytes (<= 232448 opt-in)

__global__ void __launch_bounds__(NTK, 1) fused_attn_kernel(
    const float* __restrict__ x,
    const float* __restrict__ g1, const float* __restrict__ be1)
{
    extern __shared__ char sm2[];
    const unsigned sb = smem_u32(sm2);
    float* qkv = (float*)(sm2 + QKVB);
    const int tid = threadIdx.x;
    const int w   = tid >> 5;
    const int ln  = tid & 31;
    const int g   = ln >> 2;
    const int ti  = ln & 3;
    const int rg  = w & 3;          // row group (16 rows of 64)
    const int nh  = w >> 2;         // N half
    const size_t row0 = (size_t)blockIdx.x * 64;

    if (tid == 0) { MBAR_INIT(sb + QBAR, 1); MBAR_INIT(sb + QBAR + 8, 1); }
    __syncthreads();
    if (tid == 0) {
        MBAR_EXPECT_TX(sb + QBAR, QBLK);
        BULK_LD(sb + QB0, g_WQB, QBLK, sb + QBAR);
    }

    // ---- LN1 -> fp16 A ----
    for (int r = w; r < 64; r += 8) {
        const float* xr = x + (row0 + r) * Cc;
        float s = 0.f, s2 = 0.f;
        for (int c = ln; c < Cc; c += 32) { float v = xr[c]; s += v; s2 += v*v; }
        #pragma unroll
        for (int o = 16; o; o >>= 1) {
            s  += __shfl_xor_sync(0xffffffffu, s,  o);
            s2 += __shfl_xor_sync(0xffffffffu, s2, o);
        }
        float mu = s * (1.f/Cc);
        float inv = rsqrtf(s2 * (1.f/Cc) - mu*mu + EPS);
        for (int cp = ln; cp < 96; cp += 32) {
            int c0 = cp * 2;
            float v0 = (c0   < Cc) ? (xr[c0]  -mu)*inv*g1[c0]   + be1[c0]   : 0.f;
            float v1 = (c0+1 < Cc) ? (xr[c0+1]-mu)*inv*g1[c0+1] + be1[c0+1] : 0.f;
            *(unsigned*)(sm2 + QA1 + r*400 + c0*2) = pack2h(v0, v1);
        }
    }
    __syncthreads();

    const unsigned a1addr = sb + QA1 + (unsigned)((rg*16 + (ln & 15))*400 + (ln >> 4)*16);
    const int brow = ln & 7;
    const int boff = ((ln >> 3) & 3) * 16;

    int ph0 = 0, ph1 = 0;
    for (int nt = 0; nt < 9; nt++) {
        const int c = nt & 1;
        MBAR_WAIT(sb + QBAR + 8*c, (c ? ph1 : ph0));
        if (c) ph1 ^= 1; else ph0 ^= 1;
        __syncthreads();
        if (nt < 8 && tid == 0) {
            MBAR_EXPECT_TX(sb + QBAR + 8*(c^1), QBLK);
            BULK_LD(sb + (c ? QB0 : QB1), g_WQB + (size_t)(nt+1)*QBLK, QBLK, sb + QBAR + 8*(c^1));
        }

        const unsigned bbase = sb + (c ? QB1 : QB0);
        float C1[16];
        #pragma unroll
        for (int i = 0; i < 16; i++) C1[i] = 0.f;
        for (int p = 0; p < 6; p++) {
            unsigned ah0[4], ah1[4];
            ldsm_x4(ah0, a1addr + p*64);
            ldsm_x4(ah1, a1addr + p*64 + 32);
            unsigned bf[4][4];
            #pragma unroll
            for (int na = 0; na < 4; na++)
                ldsm_x4(bf[na], bbase + (unsigned)((nh*32 + na*8 + brow)*400 + p*64 + boff));
            #pragma unroll
            for (int na = 0; na < 4; na++) mma16816(C1 + na*4, ah0, bf[na]);
            #pragma unroll
            for (int na = 0; na < 4; na++) mma16816(C1 + na*4, ah1, bf[na] + 2);
        }

        // epilogue: write into smem qkv, head-blocked: scol = mat*192 + h*32 + d
        {
            int rA = rg*16 + g;
            #pragma unroll
            for (int na = 0; na < 4; na++) {
                int col = nt*64 + nh*32 + na*8 + 2*ti;
                if (col < 540) {
                    int mat = col / 180, mm = col % 180;
                    int hh = mm / 30, d = mm % 30;
                    int scol = mat*192 + hh*32 + d;
                    *(float2*)(qkv + rA*SQ + scol)     = make_float2(C1[na*4+0], C1[na*4+1]);
                    *(float2*)(qkv + (rA+8)*SQ + scol) = make_float2(C1[na*4+2], C1[na*4+3]);
                }
            }
        }
        __syncthreads();
    }

    // ======== attention phase: 12 jobs = (local batch, head) ========
    for (int job = w; job < 12; job += 8) {
        int lb = job / 6, h = job % 6;
        const float* qrow = qkv + (lb*32 + ln)*SQ + h*32;
        const float* kbase = qkv + (size_t)lb*32*SQ + 192 + h*32;
        const float* vbase = qkv + (size_t)lb*32*SQ + 384 + h*32;

        float q[HDd];
        #pragma unroll
        for (int d = 0; d < HDd; d++) q[d] = qrow[d];

        float sc[Tt];
        #pragma unroll 4
        for (int tj = 0; tj < Tt; tj++) {
            const float4* kr = (const float4*)(kbase + tj*SQ);
            float dot = 0.f;
            #pragma unroll
            for (int i = 0; i < 7; i++) {
                float4 kv = kr[i];
                dot += q[4*i+0]*kv.x + q[4*i+1]*kv.y + q[4*i+2]*kv.z + q[4*i+3]*kv.w;
            }
            dot += q[28]*kbase[tj*SQ+28] + q[29]*kbase[tj*SQ+29];
            sc[tj] = dot * 0.18257418583505537f;
        }

        float m = -1e30f;
        #pragma unroll
        for (int tj = 0; tj < Tt; tj++) if (tj <= ln) m = fmaxf(m, sc[tj]);
        float sum = 0.f;
        #pragma unroll
        for (int tj = 0; tj < Tt; tj++) {
            float e = (tj <= ln) ? __expf(sc[tj] - m) : 0.f;
            sc[tj] = e;
            sum += e;
        }
        float inv = 1.f / sum;

        float acc[HDd];
        #pragma unroll
        for (int d = 0; d < HDd; d++) acc[d] = 0.f;
        #pragma unroll 4
        for (int tj = 0; tj < Tt; tj++) {
            float p = sc[tj] * inv;
            const float4* vr = (const float4*)(vbase + tj*SQ);
            #pragma unroll
            for (int i = 0; i < 7; i++) {
                float4 vv = vr[i];
                acc[4*i+0] += p*vv.x; acc[4*i+1] += p*vv.y;
                acc[4*i+2] += p*vv.z; acc[4*i+3] += p*vv.w;
            }
            acc[28] += p*vbase[tj*SQ+28];
            acc[29] += p*vbase[tj*SQ+29];
        }

        {
            size_t off = (row0 + lb*32 + ln) * Cc + h*HDd;
            const float* xr = x + off;
            float* og = g_X2 + off;
            #pragma unroll
            for (int d = 0; d < HDd; d++) og[d] = xr[d] + acc[d];
        }
    }
}

// ============================================================================
// Kernel 2: LN2 + MLP — 64 rows/CTA, 256 thr, 2 CTAs/SM (R13, proven)
// ============================================================================
#define A1S   0
#define A2S   25600
#define B1S_  34816
#define B2S_  60416
#define MBARS 88064
#define BIAS  88080
#define SM2_TOTAL 91152

__global__ void __launch_bounds__(NTK, 2) mlp_kernel(
    const float* __restrict__ g2, const float* __restrict__ be2,
    const float* __restrict__ b1, const float* __restrict__ b2,
    float* __restrict__ out)
{
    extern __shared__ char sm2[];
    const unsigned sb = smem_u32(sm2);
    const int tid = threadIdx.x;
    const int w   = tid >> 5;
    const int ln  = tid & 31;
    const int g   = ln >> 2;
    const int ti  = ln & 3;
    const int rg  = w & 3;
    const int nh  = w >> 2;
    const size_t row0 = (size_t)blockIdx.x * 64;
    float* b1s = (float*)(sm2 + BIAS);

    if (tid == 0) { MBAR_INIT(sb + MBARS, 1); MBAR_INIT(sb + MBARS + 8, 1); }
    __syncthreads();
    if (tid == 0) {
        MBAR_EXPECT_TX(sb + MBARS, W1BLK);
        BULK_LD(sb + B1S_, g_W1B, W1BLK, sb + MBARS);
        MBAR_EXPECT_TX(sb + MBARS + 8, W2BLK);
        BULK_LD(sb + B2S_, g_W2B, W2BLK, sb + MBARS + 8);
    }

    for (int i = tid; i < 768; i += NTK) b1s[i] = (i < Ff) ? b1[i] : 0.f;

    for (int r = w; r < 64; r += 8) {
        const float* xr = g_X2 + (row0 + r) * Cc;
        float s = 0.f, s2 = 0.f;
        for (int c = ln; c < Cc; c += 32) { float v = xr[c]; s += v; s2 += v*v; }
        #pragma unroll
        for (int o = 16; o; o >>= 1) {
            s  += __shfl_xor_sync(0xffffffffu, s,  o);
            s2 += __shfl_xor_sync(0xffffffffu, s2, o);
        }
        float mu = s * (1.f/Cc);
        float inv = rsqrtf(s2 * (1.f/Cc) - mu*mu + EPS);
        for (int cp = ln; cp < 96; cp += 32) {
            int c0 = cp * 2;
            float v0 = (c0   < Cc) ? (xr[c0]  -mu)*inv*g2[c0]   + be2[c0]   : 0.f;
            float v1 = (c0+1 < Cc) ? (xr[c0+1]-mu)*inv*g2[c0+1] + be2[c0+1] : 0.f;
            *(unsigned*)(sm2 + A1S + r*400 + c0*2) = pack2h(v0, v1);
        }
    }
    __syncthreads();

    float C2[48];
    #pragma unroll
    for (int i = 0; i < 48; i++) C2[i] = 0.f;

    const unsigned a1addr = sb + A1S + (unsigned)((rg*16 + (ln & 15))*400 + (ln >> 4)*16);
    const unsigned a2addr = sb + A2S + (unsigned)((rg*16 + (ln & 15))*144 + (ln >> 4)*16);
    const int brow = ln & 7;
    const int boff = ((ln >> 3) & 3) * 16;

    int p1 = 0, p2 = 0;
    for (int nt = 0; nt < 12; nt++) {
        MBAR_WAIT(sb + MBARS, p1); p1 ^= 1;

        float C1[16];
        #pragma unroll
        for (int i = 0; i < 16; i++) C1[i] = 0.f;
        for (int p = 0; p < 6; p++) {
            unsigned ah0[4], ah1[4];
            ldsm_x4(ah0, a1addr + p*64);
            ldsm_x4(ah1, a1addr + p*64 + 32);
            unsigned bf[4][4];
            #pragma unroll
            for (int na = 0; na < 4; na++)
                ldsm_x4(bf[na], sb + B1S_ + (unsigned)((nh*32 + na*8 + brow)*400 + p*64 + boff));
            #pragma unroll
            for (int na = 0; na < 4; na++) mma16816(C1 + na*4, ah0, bf[na]);
            #pragma unroll
            for (int na = 0; na < 4; na++) mma16816(C1 + na*4, ah1, bf[na] + 2);
        }

        {
            int rA = rg*16 + g;
            #pragma unroll
            for (int na = 0; na < 4; na++) {
                int kc = nh*32 + na*8 + 2*ti;
                int colT = nt*64 + kc;
                float bb0 = b1s[colT], bb1 = b1s[colT+1];
                *(unsigned*)(sm2 + A2S + rA*144 + kc*2) =
                    pack2h(fmaxf(C1[na*4+0]+bb0, 0.f), fmaxf(C1[na*4+1]+bb1, 0.f));
                *(unsigned*)(sm2 + A2S + (rA+8)*144 + kc*2) =
                    pack2h(fmaxf(C1[na*4+2]+bb0, 0.f), fmaxf(C1[na*4+3]+bb1, 0.f));
            }
        }

        __syncthreads();
        if (nt < 11 && tid == 0) {
            MBAR_EXPECT_TX(sb + MBARS, W1BLK);
            BULK_LD(sb + B1S_, g_W1B + (size_t)(nt+1)*W1BLK, W1BLK, sb + MBARS);
        }

        MBAR_WAIT(sb + MBARS + 8, p2); p2 ^= 1;

        for (int p = 0; p < 2; p++) {
            unsigned ah0[4], ah1[4];
            ldsm_x4(ah0, a2addr + p*64);
            ldsm_x4(ah1, a2addr + p*64 + 32);
            #pragma unroll
            for (int grp = 0; grp < 3; grp++) {
                unsigned bf[4][4];
                #pragma unroll
                for (int j = 0; j < 4; j++)
                    ldsm_x4(bf[j], sb + B2S_ + (unsigned)((nh*96 + (grp*4+j)*8 + brow)*144 + p*64 + boff));
                float* Cg = C2 + grp*16;
                #pragma unroll
                for (int j = 0; j < 4; j++) mma16816(Cg + j*4, ah0, bf[j]);
                #pragma unroll
                for (int j = 0; j < 4; j++) mma16816(Cg + j*4, ah1, bf[j] + 2);
            }
        }
        __syncthreads();
        if (nt < 11 && tid == 0) {
            MBAR_EXPECT_TX(sb + MBARS + 8, W2BLK);
            BULK_LD(sb + B2S_, g_W2B + (size_t)(nt+1)*W2BLK, W2BLK, sb + MBARS + 8);
        }
    }

    {
        size_t rA = row0 + rg*16 + g;
        size_t rB = rA + 8;
        #pragma unroll
        for (int na = 0; na < 12; na++) {
            int col = nh*96 + na*8 + 2*ti;
            if (col < Cc) {
                float b20 = __ldg(b2 + col), b21 = __ldg(b2 + col + 1);
                out[rA*Cc + col]     = C2[na*4+0] + b20 + g_X2[rA*Cc + col];
                out[rA*Cc + col + 1] = C2[na*4+1] + b21 + g_X2[rA*Cc + col + 1];
                out[rB*Cc + col]     = C2[na*4+2] + b20 + g_X2[rB*Cc + col];
                out[rB*Cc + col + 1] = C2[na*4+3] + b21 + g_X2[rB*Cc + col + 1];
            }
        }
    }
}

// ============================================================================
// Launch
// ============================================================================
extern "C" void kernel_launch(void* const* d_in, const int* in_sizes, int n_in,
                              void* d_out, int out_size) {
    const float* x   = (const float*)d_in[0];
    const float* wq  = (const float*)d_in[1];
    const float* wk  = (const float*)d_in[2];
    const float* wv  = (const float*)d_in[3];
    const float* g1  = (const float*)d_in[4];
    const float* be1 = (const float*)d_in[5];
    const float* g2  = (const float*)d_in[6];
    const float* be2 = (const float*)d_in[7];
    const float* w1  = (const float*)d_in[8];
    const float* b1  = (const float*)d_in[9];
    const float* w2  = (const float*)d_in[10];
    const float* b2  = (const float*)d_in[11];
    float* out = (float*)d_out;

    cudaFuncSetAttribute(fused_attn_kernel, cudaFuncAttributeMaxDynamicSharedMemorySize, SMF_TOTAL);
    cudaFuncSetAttribute(mlp_kernel, cudaFuncAttributeMaxDynamicSharedMemorySize, SM2_TOTAL);

    prep_all<<<148, 256>>>(wq, wk, wv, w1, w2);
    fused_attn_kernel<<<ROWS / 64, NTK, SMF_TOTAL>>>(x, g1, be1);
    mlp_kernel<<<ROWS / 64, NTK, SM2_TOTAL>>>(g2, be2, b1, b2, out);
}

// round 15
// speedup vs baseline: 1.1372x; 1.1372x over previous
#include <cuda_runtime.h>
#include <cuda_fp16.h>
#include <math.h>
#include <stdint.h>

#define Bb 4096
#define Tt 32
#define Cc 180
#define Hh 6
#define HDd 30
#define Ff 720
#define EPS 1e-5f
#define ROWS (Bb*Tt)
#define NQ 576

#define QBLK  25600
#define W1BLK 25600
#define W2BLK 27648

// ============================================================================
// Device scratch
// ============================================================================
__device__ float g_X2[(size_t)ROWS * Cc];
__device__ float g_QKVS[(size_t)ROWS * NQ];   // head-blocked: scol = mat*192 + h*32 + d
__device__ __align__(16) char g_WQB[9  * QBLK];
__device__ __align__(16) char g_W1B[12 * W1BLK];
__device__ __align__(16) char g_W2B[12 * W2BLK];

// ============================================================================
// helpers
// ============================================================================
__device__ __forceinline__ unsigned smem_u32(const void* p) {
    unsigned a;
    asm("{ .reg .u64 t; cvta.to.shared.u64 t, %1; cvt.u32.u64 %0, t; }" : "=r"(a) : "l"(p));
    return a;
}
__device__ __forceinline__ void ldsm_x4(unsigned* r, unsigned addr) {
    asm volatile("ldmatrix.sync.aligned.m8n8.x4.shared.b16 {%0,%1,%2,%3}, [%4];"
                 : "=r"(r[0]), "=r"(r[1]), "=r"(r[2]), "=r"(r[3]) : "r"(addr));
}
__device__ __forceinline__ void mma16816(float* c, const unsigned* a, const unsigned* b) {
    asm volatile(
        "mma.sync.aligned.m16n8k16.row.col.f32.f16.f16.f32 "
        "{%0,%1,%2,%3}, {%4,%5,%6,%7}, {%8,%9}, {%0,%1,%2,%3};"
        : "+f"(c[0]), "+f"(c[1]), "+f"(c[2]), "+f"(c[3])
        : "r"(a[0]), "r"(a[1]), "r"(a[2]), "r"(a[3]), "r"(b[0]), "r"(b[1]));
}
__device__ __forceinline__ unsigned pack2h(float v0, float v1) {
    __half2 h = __halves2half2(__float2half_rn(v0), __float2half_rn(v1));
    return *reinterpret_cast<unsigned*>(&h);
}
#define MBAR_INIT(mb, c) \
    asm volatile("mbarrier.init.shared.b64 [%0], %1;" :: "r"((unsigned)(mb)), "r"((unsigned)(c)) : "memory")
#define MBAR_EXPECT_TX(mb, tx) \
    asm volatile("mbarrier.arrive.expect_tx.shared.b64 _, [%0], %1;" :: "r"((unsigned)(mb)), "r"((unsigned)(tx)) : "memory")
#define MBAR_WAIT(mb, par) do { \
    unsigned _m = (unsigned)(mb); unsigned _p = (unsigned)(par); unsigned _d; \
    asm volatile("{\n\t.reg .pred p;\n\t" \
        "mbarrier.try_wait.parity.acquire.cta.shared::cta.b64 p, [%1], %2;\n\t" \
        "selp.b32 %0, 1, 0, p;\n\t}" : "=r"(_d) : "r"(_m), "r"(_p) : "memory"); \
    if (!_d) { \
        asm volatile("{\n\t.reg .pred P1;\n\t" \
            "WL_%=:\n\t" \
            "mbarrier.try_wait.parity.acquire.cta.shared::cta.b64 P1, [%0], %1, 0x989680;\n\t" \
            "@P1 bra.uni WD_%=;\n\t" \
            "bra.uni WL_%=;\n\t" \
            "WD_%=:\n\t}" :: "r"(_m), "r"(_p) : "memory"); \
    } } while (0)
#define BULK_LD(dst, src, sz, mb) \
    asm volatile("cp.async.bulk.shared::cluster.global.mbarrier::complete_tx::bytes [%0], [%1], %2, [%3];" \
                 :: "r"((unsigned)(dst)), "l"(src), "r"((unsigned)(sz)), "r"((unsigned)(mb)) : "memory")

// ============================================================================
// Prep
// ============================================================================
__global__ void prep_all(const float* __restrict__ wq, const float* __restrict__ wk,
                         const float* __restrict__ wv, const float* __restrict__ w1,
                         const float* __restrict__ w2) {
    const int NWQ = NQ * 192, NW1 = 768 * 192, NW2 = 192 * 768;
    for (int i = blockIdx.x * blockDim.x + threadIdx.x; i < NWQ + NW1 + NW2;
         i += gridDim.x * blockDim.x) {
        float v = 0.f;
        char* p;
        if (i < NWQ) {
            int n = i / 192, k = i % 192;
            if (n < 540 && k < Cc) {
                int mat = n / Cc, m = n % Cc;
                int hh = m / HDd, d = m % HDd;
                const float* W = (mat == 0 ? wq : (mat == 1 ? wk : wv));
                v = W[(size_t)hh * (Cc*HDd) + (size_t)k * HDd + d];
            }
            p = g_WQB + (n >> 6) * QBLK + (n & 63) * 400 + k * 2;
        } else if (i < NWQ + NW1) {
            int j = i - NWQ;
            int n = j / 192, k = j % 192;
            if (n < Ff && k < Cc) v = w1[(size_t)k * Ff + n];
            p = g_W1B + (n >> 6) * W1BLK + (n & 63) * 400 + k * 2;
        } else {
            int j = i - NWQ - NW1;
            int n = j / 768, k = j % 768;
            if (n < Cc && k < Ff) v = w2[(size_t)k * Cc + n];
            p = g_W2B + (k >> 6) * W2BLK + n * 144 + (k & 63) * 2;
        }
        *(__half*)p = __float2half_rn(v);
    }
}

// ============================================================================
// Kernel 1: LN1 + QKV GEMM — 64 rows/CTA, 256 thr, 2 CTAs/SM (R13)
//   epilogue writes g_QKVS head-blocked.
// ============================================================================
#define NTK 256
#define QA1   0
#define QB0   25600
#define QB1   51200
#define QBAR  76800
#define SMQ_TOTAL 76928

__global__ void __launch_bounds__(NTK, 2) ln1qkv_kernel(
    const float* __restrict__ x,
    const float* __restrict__ g1, const float* __restrict__ be1)
{
    extern __shared__ char sm2[];
    const unsigned sb = smem_u32(sm2);
    const int tid = threadIdx.x;
    const int w   = tid >> 5;
    const int ln  = tid & 31;
    const int g   = ln >> 2;
    const int ti  = ln & 3;
    const int rg  = w & 3;
    const int nh  = w >> 2;
    const size_t row0 = (size_t)blockIdx.x * 64;

    if (tid == 0) { MBAR_INIT(sb + QBAR, 1); MBAR_INIT(sb + QBAR + 8, 1); }
    __syncthreads();
    if (tid == 0) {
        MBAR_EXPECT_TX(sb + QBAR, QBLK);
        BULK_LD(sb + QB0, g_WQB, QBLK, sb + QBAR);
    }

    for (int r = w; r < 64; r += 8) {
        const float* xr = x + (row0 + r) * Cc;
        float s = 0.f, s2 = 0.f;
        for (int c = ln; c < Cc; c += 32) { float v = xr[c]; s += v; s2 += v*v; }
        #pragma unroll
        for (int o = 16; o; o >>= 1) {
            s  += __shfl_xor_sync(0xffffffffu, s,  o);
            s2 += __shfl_xor_sync(0xffffffffu, s2, o);
        }
        float mu = s * (1.f/Cc);
        float inv = rsqrtf(s2 * (1.f/Cc) - mu*mu + EPS);
        for (int cp = ln; cp < 96; cp += 32) {
            int c0 = cp * 2;
            float v0 = (c0   < Cc) ? (xr[c0]  -mu)*inv*g1[c0]   + be1[c0]   : 0.f;
            float v1 = (c0+1 < Cc) ? (xr[c0+1]-mu)*inv*g1[c0+1] + be1[c0+1] : 0.f;
            *(unsigned*)(sm2 + QA1 + r*400 + c0*2) = pack2h(v0, v1);
        }
    }
    __syncthreads();

    const unsigned a1addr = sb + QA1 + (unsigned)((rg*16 + (ln & 15))*400 + (ln >> 4)*16);
    const int brow = ln & 7;
    const int boff = ((ln >> 3) & 3) * 16;

    int ph0 = 0, ph1 = 0;
    for (int nt = 0; nt < 9; nt++) {
        const int c = nt & 1;
        MBAR_WAIT(sb + QBAR + 8*c, (c ? ph1 : ph0));
        if (c) ph1 ^= 1; else ph0 ^= 1;
        __syncthreads();
        if (nt < 8 && tid == 0) {
            MBAR_EXPECT_TX(sb + QBAR + 8*(c^1), QBLK);
            BULK_LD(sb + (c ? QB0 : QB1), g_WQB + (size_t)(nt+1)*QBLK, QBLK, sb + QBAR + 8*(c^1));
        }

        const unsigned bbase = sb + (c ? QB1 : QB0);
        float C1[16];
        #pragma unroll
        for (int i = 0; i < 16; i++) C1[i] = 0.f;
        for (int p = 0; p < 6; p++) {
            unsigned ah0[4], ah1[4];
            ldsm_x4(ah0, a1addr + p*64);
            ldsm_x4(ah1, a1addr + p*64 + 32);
            unsigned bf[4][4];
            #pragma unroll
            for (int na = 0; na < 4; na++)
                ldsm_x4(bf[na], bbase + (unsigned)((nh*32 + na*8 + brow)*400 + p*64 + boff));
            #pragma unroll
            for (int na = 0; na < 4; na++) mma16816(C1 + na*4, ah0, bf[na]);
            #pragma unroll
            for (int na = 0; na < 4; na++) mma16816(C1 + na*4, ah1, bf[na] + 2);
        }

        // epilogue: head-blocked scatter: scol = mat*192 + h*32 + d (d even here)
        {
            size_t rA = row0 + rg*16 + g;
            size_t rB = rA + 8;
            #pragma unroll
            for (int na = 0; na < 4; na++) {
                int col = nt*64 + nh*32 + na*8 + 2*ti;
                if (col < 540) {
                    int mat = col / 180, mm = col % 180;
                    int hh = mm / 30, d = mm % 30;
                    int scol = mat*192 + hh*32 + d;
                    *(float2*)(g_QKVS + rA*NQ + scol) = make_float2(C1[na*4+0], C1[na*4+1]);
                    *(float2*)(g_QKVS + rB*NQ + scol) = make_float2(C1[na*4+2], C1[na*4+3]);
                }
            }
        }
    }
}

// ============================================================================
// Kernel 2: softmax + A@V + residual — float4 staging from head-blocked QKVS
// ============================================================================
#define PD32 32
#define SMH_TOTAL (6*Tt*PD32)

__global__ void __launch_bounds__(64, 8) attn2_kernel(const float* __restrict__ x)
{
    extern __shared__ float sm[];
    const int b   = blockIdx.x;
    const int hp  = blockIdx.y;
    const int tid = threadIdx.x;
    const int wi  = tid >> 5;
    const int ln  = tid & 31;

    // stage q,k,v for heads 2hp, 2hp+1: 6 blocks x 32 rows x 32 floats, pure float4
    const float* base = g_QKVS + (size_t)b * (Tt*NQ);
    for (int e = tid; e < 6*32*8; e += 64) {
        int blk = e >> 8;            // 0..5 = m*2 + hl
        int rem = e & 255;
        int r = rem >> 3, q4 = rem & 7;
        int m = blk >> 1, hl = blk & 1;
        float4 v = *(const float4*)(base + (size_t)r*NQ + m*192 + (hp*2+hl)*32 + q4*4);
        *(float4*)(sm + m*(2*Tt*PD32) + hl*(Tt*PD32) + r*PD32 + q4*4) = v;
    }
    __syncthreads();

    const float* qsw = sm + 0*(2*Tt*PD32) + wi*(Tt*PD32);
    const float* ksw = sm + 1*(2*Tt*PD32) + wi*(Tt*PD32);
    const float* vsw = sm + 2*(2*Tt*PD32) + wi*(Tt*PD32);

    float q[HDd];
    #pragma unroll
    for (int d = 0; d < HDd; d++) q[d] = qsw[ln*PD32 + d];

    float sc[Tt];
    #pragma unroll 4
    for (int tj = 0; tj < Tt; tj++) {
        const float4* kr = (const float4*)(ksw + tj*PD32);
        float dot = 0.f;
        #pragma unroll
        for (int i = 0; i < 7; i++) {
            float4 kv = kr[i];
            dot += q[4*i+0]*kv.x + q[4*i+1]*kv.y + q[4*i+2]*kv.z + q[4*i+3]*kv.w;
        }
        dot += q[28]*ksw[tj*PD32+28] + q[29]*ksw[tj*PD32+29];
        sc[tj] = dot * 0.18257418583505537f;
    }

    float m = -1e30f;
    #pragma unroll
    for (int tj = 0; tj < Tt; tj++) if (tj <= ln) m = fmaxf(m, sc[tj]);
    float sum = 0.f;
    #pragma unroll
    for (int tj = 0; tj < Tt; tj++) {
        float e = (tj <= ln) ? __expf(sc[tj] - m) : 0.f;
        sc[tj] = e;
        sum += e;
    }
    float inv = 1.f / sum;

    float acc[HDd];
    #pragma unroll
    for (int d = 0; d < HDd; d++) acc[d] = 0.f;
    #pragma unroll 4
    for (int tj = 0; tj < Tt; tj++) {
        float p = sc[tj] * inv;
        const float4* vr = (const float4*)(vsw + tj*PD32);
        #pragma unroll
        for (int i = 0; i < 7; i++) {
            float4 vv = vr[i];
            acc[4*i+0] += p*vv.x; acc[4*i+1] += p*vv.y;
            acc[4*i+2] += p*vv.z; acc[4*i+3] += p*vv.w;
        }
        acc[28] += p*vsw[tj*PD32+28];
        acc[29] += p*vsw[tj*PD32+29];
    }

    {
        size_t off = ((size_t)b*Tt + ln) * Cc + (hp*2 + wi)*HDd;
        const float* xr = x + off;
        float* og = g_X2 + off;
        #pragma unroll
        for (int d = 0; d < HDd; d++) og[d] = xr[d] + acc[d];
    }
}

// ============================================================================
// Kernel 3: LN2 + MLP — 64 rows/CTA, 256 thr, 2 CTAs/SM (R13, proven)
// ============================================================================
#define A1S   0
#define A2S   25600
#define B1S_  34816
#define B2S_  60416
#define MBARS 88064
#define BIAS  88080
#define SM2_TOTAL 91152

__global__ void __launch_bounds__(NTK, 2) mlp_kernel(
    const float* __restrict__ g2, const float* __restrict__ be2,
    const float* __restrict__ b1, const float* __restrict__ b2,
    float* __restrict__ out)
{
    extern __shared__ char sm2[];
    const unsigned sb = smem_u32(sm2);
    const int tid = threadIdx.x;
    const int w   = tid >> 5;
    const int ln  = tid & 31;
    const int g   = ln >> 2;
    const int ti  = ln & 3;
    const int rg  = w & 3;
    const int nh  = w >> 2;
    const size_t row0 = (size_t)blockIdx.x * 64;
    float* b1s = (float*)(sm2 + BIAS);

    if (tid == 0) { MBAR_INIT(sb + MBARS, 1); MBAR_INIT(sb + MBARS + 8, 1); }
    __syncthreads();
    if (tid == 0) {
        MBAR_EXPECT_TX(sb + MBARS, W1BLK);
        BULK_LD(sb + B1S_, g_W1B, W1BLK, sb + MBARS);
        MBAR_EXPECT_TX(sb + MBARS + 8, W2BLK);
        BULK_LD(sb + B2S_, g_W2B, W2BLK, sb + MBARS + 8);
    }

    for (int i = tid; i < 768; i += NTK) b1s[i] = (i < Ff) ? b1[i] : 0.f;

    for (int r = w; r < 64; r += 8) {
        const float* xr = g_X2 + (row0 + r) * Cc;
        float s = 0.f, s2 = 0.f;
        for (int c = ln; c < Cc; c += 32) { float v = xr[c]; s += v; s2 += v*v; }
        #pragma unroll
        for (int o = 16; o; o >>= 1) {
            s  += __shfl_xor_sync(0xffffffffu, s,  o);
            s2 += __shfl_xor_sync(0xffffffffu, s2, o);
        }
        float mu = s * (1.f/Cc);
        float inv = rsqrtf(s2 * (1.f/Cc) - mu*mu + EPS);
        for (int cp = ln; cp < 96; cp += 32) {
            int c0 = cp * 2;
            float v0 = (c0   < Cc) ? (xr[c0]  -mu)*inv*g2[c0]   + be2[c0]   : 0.f;
            float v1 = (c0+1 < Cc) ? (xr[c0+1]-mu)*inv*g2[c0+1] + be2[c0+1] : 0.f;
            *(unsigned*)(sm2 + A1S + r*400 + c0*2) = pack2h(v0, v1);
        }
    }
    __syncthreads();

    float C2[48];
    #pragma unroll
    for (int i = 0; i < 48; i++) C2[i] = 0.f;

    const unsigned a1addr = sb + A1S + (unsigned)((rg*16 + (ln & 15))*400 + (ln >> 4)*16);
    const unsigned a2addr = sb + A2S + (unsigned)((rg*16 + (ln & 15))*144 + (ln >> 4)*16);
    const int brow = ln & 7;
    const int boff = ((ln >> 3) & 3) * 16;

    int p1 = 0, p2 = 0;
    for (int nt = 0; nt < 12; nt++) {
        MBAR_WAIT(sb + MBARS, p1); p1 ^= 1;

        float C1[16];
        #pragma unroll
        for (int i = 0; i < 16; i++) C1[i] = 0.f;
        for (int p = 0; p < 6; p++) {
            unsigned ah0[4], ah1[4];
            ldsm_x4(ah0, a1addr + p*64);
            ldsm_x4(ah1, a1addr + p*64 + 32);
            unsigned bf[4][4];
            #pragma unroll
            for (int na = 0; na < 4; na++)
                ldsm_x4(bf[na], sb + B1S_ + (unsigned)((nh*32 + na*8 + brow)*400 + p*64 + boff));
            #pragma unroll
            for (int na = 0; na < 4; na++) mma16816(C1 + na*4, ah0, bf[na]);
            #pragma unroll
            for (int na = 0; na < 4; na++) mma16816(C1 + na*4, ah1, bf[na] + 2);
        }

        {
            int rA = rg*16 + g;
            #pragma unroll
            for (int na = 0; na < 4; na++) {
                int kc = nh*32 + na*8 + 2*ti;
                int colT = nt*64 + kc;
                float bb0 = b1s[colT], bb1 = b1s[colT+1];
                *(unsigned*)(sm2 + A2S + rA*144 + kc*2) =
                    pack2h(fmaxf(C1[na*4+0]+bb0, 0.f), fmaxf(C1[na*4+1]+bb1, 0.f));
                *(unsigned*)(sm2 + A2S + (rA+8)*144 + kc*2) =
                    pack2h(fmaxf(C1[na*4+2]+bb0, 0.f), fmaxf(C1[na*4+3]+bb1, 0.f));
            }
        }

        __syncthreads();
        if (nt < 11 && tid == 0) {
            MBAR_EXPECT_TX(sb + MBARS, W1BLK);
            BULK_LD(sb + B1S_, g_W1B + (size_t)(nt+1)*W1BLK, W1BLK, sb + MBARS);
        }

        MBAR_WAIT(sb + MBARS + 8, p2); p2 ^= 1;

        for (int p = 0; p < 2; p++) {
            unsigned ah0[4], ah1[4];
            ldsm_x4(ah0, a2addr + p*64);
            ldsm_x4(ah1, a2addr + p*64 + 32);
            #pragma unroll
            for (int grp = 0; grp < 3; grp++) {
                unsigned bf[4][4];
                #pragma unroll
                for (int j = 0; j < 4; j++)
                    ldsm_x4(bf[j], sb + B2S_ + (unsigned)((nh*96 + (grp*4+j)*8 + brow)*144 + p*64 + boff));
                float* Cg = C2 + grp*16;
                #pragma unroll
                for (int j = 0; j < 4; j++) mma16816(Cg + j*4, ah0, bf[j]);
                #pragma unroll
                for (int j = 0; j < 4; j++) mma16816(Cg + j*4, ah1, bf[j] + 2);
            }
        }
        __syncthreads();
        if (nt < 11 && tid == 0) {
            MBAR_EXPECT_TX(sb + MBARS + 8, W2BLK);
            BULK_LD(sb + B2S_, g_W2B + (size_t)(nt+1)*W2BLK, W2BLK, sb + MBARS + 8);
        }
    }

    {
        size_t rA = row0 + rg*16 + g;
        size_t rB = rA + 8;
        #pragma unroll
        for (int na = 0; na < 12; na++) {
            int col = nh*96 + na*8 + 2*ti;
            if (col < Cc) {
                float b20 = __ldg(b2 + col), b21 = __ldg(b2 + col + 1);
                out[rA*Cc + col]     = C2[na*4+0] + b20 + g_X2[rA*Cc + col];
                out[rA*Cc + col + 1] = C2[na*4+1] + b21 + g_X2[rA*Cc + col + 1];
                out[rB*Cc + col]     = C2[na*4+2] + b20 + g_X2[rB*Cc + col];
                out[rB*Cc + col + 1] = C2[na*4+3] + b21 + g_X2[rB*Cc + col + 1];
            }
        }
    }
}

// ============================================================================
// Launch
// ============================================================================
extern "C" void kernel_launch(void* const* d_in, const int* in_sizes, int n_in,
                              void* d_out, int out_size) {
    const float* x   = (const float*)d_in[0];
    const float* wq  = (const float*)d_in[1];
    const float* wk  = (const float*)d_in[2];
    const float* wv  = (const float*)d_in[3];
    const float* g1  = (const float*)d_in[4];
    const float* be1 = (const float*)d_in[5];
    const float* g2  = (const float*)d_in[6];
    const float* be2 = (const float*)d_in[7];
    const float* w1  = (const float*)d_in[8];
    const float* b1  = (const float*)d_in[9];
    const float* w2  = (const float*)d_in[10];
    const float* b2  = (const float*)d_in[11];
    float* out = (float*)d_out;

    cudaFuncSetAttribute(ln1qkv_kernel, cudaFuncAttributeMaxDynamicSharedMemorySize, SMQ_TOTAL);
    cudaFuncSetAttribute(attn2_kernel, cudaFuncAttributeMaxDynamicSharedMemorySize,
                         SMH_TOTAL * (int)sizeof(float));
    cudaFuncSetAttribute(mlp_kernel, cudaFuncAttributeMaxDynamicSharedMemorySize, SM2_TOTAL);

    prep_all<<<148, 256>>>(wq, wk, wv, w1, w2);
    ln1qkv_kernel<<<ROWS / 64, NTK, SMQ_TOTAL>>>(x, g1, be1);
    dim3 agrid(Bb, 3);
    attn2_kernel<<<agrid, 64, SMH_TOTAL * sizeof(float)>>>(x);
    mlp_kernel<<<ROWS / 64, NTK, SM2_TOTAL>>>(g2, be2, b1, b2, out);
}

// round 16
// speedup vs baseline: 1.2823x; 1.1277x over previous
#include <cuda_runtime.h>
#include <cuda_fp16.h>
#include <math.h>
#include <stdint.h>

#define Bb 4096
#define Tt 32
#define Cc 180
#define Hh 6
#define HDd 30
#define Ff 720
#define EPS 1e-5f
#define ROWS (Bb*Tt)
#define NQ 576

#define QBLK  25600
#define W1BLK 25600
#define W2BLK 27648

// ============================================================================
// Device scratch
// ============================================================================
__device__ float g_X2[(size_t)ROWS * Cc];
__device__ float g_QKVS[(size_t)ROWS * NQ];   // head-blocked: scol = mat*192 + h*32 + d
__device__ __align__(16) char g_WQB[9  * QBLK];
__device__ __align__(16) char g_W1B[12 * W1BLK];
__device__ __align__(16) char g_W2B[12 * W2BLK];

// ============================================================================
// helpers
// ============================================================================
__device__ __forceinline__ unsigned smem_u32(const void* p) {
    unsigned a;
    asm("{ .reg .u64 t; cvta.to.shared.u64 t, %1; cvt.u32.u64 %0, t; }" : "=r"(a) : "l"(p));
    return a;
}
__device__ __forceinline__ void ldsm_x4(unsigned* r, unsigned addr) {
    asm volatile("ldmatrix.sync.aligned.m8n8.x4.shared.b16 {%0,%1,%2,%3}, [%4];"
                 : "=r"(r[0]), "=r"(r[1]), "=r"(r[2]), "=r"(r[3]) : "r"(addr));
}
__device__ __forceinline__ void mma16816(float* c, const unsigned* a, const unsigned* b) {
    asm volatile(
        "mma.sync.aligned.m16n8k16.row.col.f32.f16.f16.f32 "
        "{%0,%1,%2,%3}, {%4,%5,%6,%7}, {%8,%9}, {%0,%1,%2,%3};"
        : "+f"(c[0]), "+f"(c[1]), "+f"(c[2]), "+f"(c[3])
        : "r"(a[0]), "r"(a[1]), "r"(a[2]), "r"(a[3]), "r"(b[0]), "r"(b[1]));
}
__device__ __forceinline__ unsigned pack2h(float v0, float v1) {
    __half2 h = __halves2half2(__float2half_rn(v0), __float2half_rn(v1));
    return *reinterpret_cast<unsigned*>(&h);
}
#define MBAR_INIT(mb, c) \
    asm volatile("mbarrier.init.shared.b64 [%0], %1;" :: "r"((unsigned)(mb)), "r"((unsigned)(c)) : "memory")
#define MBAR_EXPECT_TX(mb, tx) \
    asm volatile("mbarrier.arrive.expect_tx.shared.b64 _, [%0], %1;" :: "r"((unsigned)(mb)), "r"((unsigned)(tx)) : "memory")
#define MBAR_WAIT(mb, par) do { \
    unsigned _m = (unsigned)(mb); unsigned _p = (unsigned)(par); unsigned _d; \
    asm volatile("{\n\t.reg .pred p;\n\t" \
        "mbarrier.try_wait.parity.acquire.cta.shared::cta.b64 p, [%1], %2;\n\t" \
        "selp.b32 %0, 1, 0, p;\n\t}" : "=r"(_d) : "r"(_m), "r"(_p) : "memory"); \
    if (!_d) { \
        asm volatile("{\n\t.reg .pred P1;\n\t" \
            "WL_%=:\n\t" \
            "mbarrier.try_wait.parity.acquire.cta.shared::cta.b64 P1, [%0], %1, 0x989680;\n\t" \
            "@P1 bra.uni WD_%=;\n\t" \
            "bra.uni WL_%=;\n\t" \
            "WD_%=:\n\t}" :: "r"(_m), "r"(_p) : "memory"); \
    } } while (0)
#define BULK_LD(dst, src, sz, mb) \
    asm volatile("cp.async.bulk.shared::cluster.global.mbarrier::complete_tx::bytes [%0], [%1], %2, [%3];" \
                 :: "r"((unsigned)(dst)), "l"(src), "r"((unsigned)(sz)), "r"((unsigned)(mb)) : "memory")

// ============================================================================
// Prep
// ============================================================================
__global__ void prep_all(const float* __restrict__ wq, const float* __restrict__ wk,
                         const float* __restrict__ wv, const float* __restrict__ w1,
                         const float* __restrict__ w2) {
    const int NWQ = NQ * 192, NW1 = 768 * 192, NW2 = 192 * 768;
    for (int i = blockIdx.x * blockDim.x + threadIdx.x; i < NWQ + NW1 + NW2;
         i += gridDim.x * blockDim.x) {
        float v = 0.f;
        char* p;
        if (i < NWQ) {
            int n = i / 192, k = i % 192;
            if (n < 540 && k < Cc) {
                int mat = n / Cc, m = n % Cc;
                int hh = m / HDd, d = m % HDd;
                const float* W = (mat == 0 ? wq : (mat == 1 ? wk : wv));
                v = W[(size_t)hh * (Cc*HDd) + (size_t)k * HDd + d];
            }
            p = g_WQB + (n >> 6) * QBLK + (n & 63) * 400 + k * 2;
        } else if (i < NWQ + NW1) {
            int j = i - NWQ;
            int n = j / 192, k = j % 192;
            if (n < Ff && k < Cc) v = w1[(size_t)k * Ff + n];
            p = g_W1B + (n >> 6) * W1BLK + (n & 63) * 400 + k * 2;
        } else {
            int j = i - NWQ - NW1;
            int n = j / 768, k = j % 768;
            if (n < Cc && k < Ff) v = w2[(size_t)k * Cc + n];
            p = g_W2B + (k >> 6) * W2BLK + n * 144 + (k & 63) * 2;
        }
        *(__half*)p = __float2half_rn(v);
    }
}

// ============================================================================
// Kernel 1: LN1 + QKV GEMM — 32 rows/CTA, 256 thr, 3 CTAs/SM
// ============================================================================
#define NTK 256
#define QA1   0
#define QB0   12800
#define QB1   38400
#define QBAR  64000
#define SMQ_TOTAL 64032

__global__ void __launch_bounds__(NTK, 3) ln1qkv_kernel(
    const float* __restrict__ x,
    const float* __restrict__ g1, const float* __restrict__ be1)
{
    extern __shared__ char sm2[];
    const unsigned sb = smem_u32(sm2);
    const int tid = threadIdx.x;
    const int w   = tid >> 5;
    const int ln  = tid & 31;
    const int g   = ln >> 2;
    const int ti  = ln & 3;
    const int rg  = w & 1;          // row group (16 rows of 32)
    const int nh  = w >> 1;         // N quarter (16 cols of 64)
    const size_t row0 = (size_t)blockIdx.x * 32;

    if (tid == 0) { MBAR_INIT(sb + QBAR, 1); MBAR_INIT(sb + QBAR + 8, 1); }
    __syncthreads();
    if (tid == 0) {
        MBAR_EXPECT_TX(sb + QBAR, QBLK);
        BULK_LD(sb + QB0, g_WQB, QBLK, sb + QBAR);
    }

    // ---- LN1 -> fp16 A ----
    for (int r = w; r < 32; r += 8) {
        const float* xr = x + (row0 + r) * Cc;
        float s = 0.f, s2 = 0.f;
        for (int c = ln; c < Cc; c += 32) { float v = xr[c]; s += v; s2 += v*v; }
        #pragma unroll
        for (int o = 16; o; o >>= 1) {
            s  += __shfl_xor_sync(0xffffffffu, s,  o);
            s2 += __shfl_xor_sync(0xffffffffu, s2, o);
        }
        float mu = s * (1.f/Cc);
        float inv = rsqrtf(s2 * (1.f/Cc) - mu*mu + EPS);
        for (int cp = ln; cp < 96; cp += 32) {
            int c0 = cp * 2;
            float v0 = (c0   < Cc) ? (xr[c0]  -mu)*inv*g1[c0]   + be1[c0]   : 0.f;
            float v1 = (c0+1 < Cc) ? (xr[c0+1]-mu)*inv*g1[c0+1] + be1[c0+1] : 0.f;
            *(unsigned*)(sm2 + QA1 + r*400 + c0*2) = pack2h(v0, v1);
        }
    }
    __syncthreads();

    const unsigned a1addr = sb + QA1 + (unsigned)((rg*16 + (ln & 15))*400 + (ln >> 4)*16);
    const int brow = ln & 7;
    const int boff = ((ln >> 3) & 3) * 16;

    int ph0 = 0, ph1 = 0;
    for (int nt = 0; nt < 9; nt++) {
        const int c = nt & 1;
        MBAR_WAIT(sb + QBAR + 8*c, (c ? ph1 : ph0));
        if (c) ph1 ^= 1; else ph0 ^= 1;
        __syncthreads();
        if (nt < 8 && tid == 0) {
            MBAR_EXPECT_TX(sb + QBAR + 8*(c^1), QBLK);
            BULK_LD(sb + (c ? QB0 : QB1), g_WQB + (size_t)(nt+1)*QBLK, QBLK, sb + QBAR + 8*(c^1));
        }

        const unsigned bbase = sb + (c ? QB1 : QB0);
        float C1[8];
        #pragma unroll
        for (int i = 0; i < 8; i++) C1[i] = 0.f;
        for (int p = 0; p < 6; p++) {
            unsigned ah0[4], ah1[4];
            ldsm_x4(ah0, a1addr + p*64);
            ldsm_x4(ah1, a1addr + p*64 + 32);
            unsigned bf[2][4];
            #pragma unroll
            for (int na = 0; na < 2; na++)
                ldsm_x4(bf[na], bbase + (unsigned)((nh*16 + na*8 + brow)*400 + p*64 + boff));
            #pragma unroll
            for (int na = 0; na < 2; na++) mma16816(C1 + na*4, ah0, bf[na]);
            #pragma unroll
            for (int na = 0; na < 2; na++) mma16816(C1 + na*4, ah1, bf[na] + 2);
        }

        // epilogue: head-blocked scatter: scol = mat*192 + h*32 + d (d even)
        {
            size_t rA = row0 + rg*16 + g;
            size_t rB = rA + 8;
            #pragma unroll
            for (int na = 0; na < 2; na++) {
                int col = nt*64 + nh*16 + na*8 + 2*ti;
                if (col < 540) {
                    int mat = col / 180, mm = col % 180;
                    int hh = mm / 30, d = mm % 30;
                    int scol = mat*192 + hh*32 + d;
                    *(float2*)(g_QKVS + rA*NQ + scol) = make_float2(C1[na*4+0], C1[na*4+1]);
                    *(float2*)(g_QKVS + rB*NQ + scol) = make_float2(C1[na*4+2], C1[na*4+3]);
                }
            }
        }
    }
}

// ============================================================================
// Kernel 2: softmax + A@V + residual — float4 staging (R15, proven)
// ============================================================================
#define PD32 32
#define SMH_TOTAL (6*Tt*PD32)

__global__ void __launch_bounds__(64, 8) attn2_kernel(const float* __restrict__ x)
{
    extern __shared__ float sm[];
    const int b   = blockIdx.x;
    const int hp  = blockIdx.y;
    const int tid = threadIdx.x;
    const int wi  = tid >> 5;
    const int ln  = tid & 31;

    const float* base = g_QKVS + (size_t)b * (Tt*NQ);
    for (int e = tid; e < 6*32*8; e += 64) {
        int blk = e >> 8;
        int rem = e & 255;
        int r = rem >> 3, q4 = rem & 7;
        int m = blk >> 1, hl = blk & 1;
        float4 v = *(const float4*)(base + (size_t)r*NQ + m*192 + (hp*2+hl)*32 + q4*4);
        *(float4*)(sm + m*(2*Tt*PD32) + hl*(Tt*PD32) + r*PD32 + q4*4) = v;
    }
    __syncthreads();

    const float* qsw = sm + 0*(2*Tt*PD32) + wi*(Tt*PD32);
    const float* ksw = sm + 1*(2*Tt*PD32) + wi*(Tt*PD32);
    const float* vsw = sm + 2*(2*Tt*PD32) + wi*(Tt*PD32);

    float q[HDd];
    #pragma unroll
    for (int d = 0; d < HDd; d++) q[d] = qsw[ln*PD32 + d];

    float sc[Tt];
    #pragma unroll 4
    for (int tj = 0; tj < Tt; tj++) {
        const float4* kr = (const float4*)(ksw + tj*PD32);
        float dot = 0.f;
        #pragma unroll
        for (int i = 0; i < 7; i++) {
            float4 kv = kr[i];
            dot += q[4*i+0]*kv.x + q[4*i+1]*kv.y + q[4*i+2]*kv.z + q[4*i+3]*kv.w;
        }
        dot += q[28]*ksw[tj*PD32+28] + q[29]*ksw[tj*PD32+29];
        sc[tj] = dot * 0.18257418583505537f;
    }

    float m = -1e30f;
    #pragma unroll
    for (int tj = 0; tj < Tt; tj++) if (tj <= ln) m = fmaxf(m, sc[tj]);
    float sum = 0.f;
    #pragma unroll
    for (int tj = 0; tj < Tt; tj++) {
        float e = (tj <= ln) ? __expf(sc[tj] - m) : 0.f;
        sc[tj] = e;
        sum += e;
    }
    float inv = 1.f / sum;

    float acc[HDd];
    #pragma unroll
    for (int d = 0; d < HDd; d++) acc[d] = 0.f;
    #pragma unroll 4
    for (int tj = 0; tj < Tt; tj++) {
        float p = sc[tj] * inv;
        const float4* vr = (const float4*)(vsw + tj*PD32);
        #pragma unroll
        for (int i = 0; i < 7; i++) {
            float4 vv = vr[i];
            acc[4*i+0] += p*vv.x; acc[4*i+1] += p*vv.y;
            acc[4*i+2] += p*vv.z; acc[4*i+3] += p*vv.w;
        }
        acc[28] += p*vsw[tj*PD32+28];
        acc[29] += p*vsw[tj*PD32+29];
    }

    {
        size_t off = ((size_t)b*Tt + ln) * Cc + (hp*2 + wi)*HDd;
        const float* xr = x + off;
        float* og = g_X2 + off;
        #pragma unroll
        for (int d = 0; d < HDd; d++) og[d] = xr[d] + acc[d];
    }
}

// ============================================================================
// Kernel 3: LN2 + MLP — 32 rows/CTA, 256 thr, 3 CTAs/SM
// ============================================================================
#define A1S   0
#define A2S   12800     // 32 x 144B = 4608
#define B1S_  17408     // 25600
#define B2S_  43008     // 27648
#define MBARS 70656
#define SM2_TOTAL 70688

__global__ void __launch_bounds__(NTK, 3) mlp_kernel(
    const float* __restrict__ g2, const float* __restrict__ be2,
    const float* __restrict__ b1, const float* __restrict__ b2,
    float* __restrict__ out)
{
    extern __shared__ char sm2[];
    const unsigned sb = smem_u32(sm2);
    const int tid = threadIdx.x;
    const int w   = tid >> 5;
    const int ln  = tid & 31;
    const int g   = ln >> 2;
    const int ti  = ln & 3;
    const int rg  = w & 1;          // row group (16 of 32)
    const int nh  = w >> 1;         // N quarter
    const size_t row0 = (size_t)blockIdx.x * 32;

    if (tid == 0) { MBAR_INIT(sb + MBARS, 1); MBAR_INIT(sb + MBARS + 8, 1); }
    __syncthreads();
    if (tid == 0) {
        MBAR_EXPECT_TX(sb + MBARS, W1BLK);
        BULK_LD(sb + B1S_, g_W1B, W1BLK, sb + MBARS);
        MBAR_EXPECT_TX(sb + MBARS + 8, W2BLK);
        BULK_LD(sb + B2S_, g_W2B, W2BLK, sb + MBARS + 8);
    }

    // ---- LN2 -> fp16 A1 ----
    for (int r = w; r < 32; r += 8) {
        const float* xr = g_X2 + (row0 + r) * Cc;
        float s = 0.f, s2 = 0.f;
        for (int c = ln; c < Cc; c += 32) { float v = xr[c]; s += v; s2 += v*v; }
        #pragma unroll
        for (int o = 16; o; o >>= 1) {
            s  += __shfl_xor_sync(0xffffffffu, s,  o);
            s2 += __shfl_xor_sync(0xffffffffu, s2, o);
        }
        float mu = s * (1.f/Cc);
        float inv = rsqrtf(s2 * (1.f/Cc) - mu*mu + EPS);
        for (int cp = ln; cp < 96; cp += 32) {
            int c0 = cp * 2;
            float v0 = (c0   < Cc) ? (xr[c0]  -mu)*inv*g2[c0]   + be2[c0]   : 0.f;
            float v1 = (c0+1 < Cc) ? (xr[c0+1]-mu)*inv*g2[c0+1] + be2[c0+1] : 0.f;
            *(unsigned*)(sm2 + A1S + r*400 + c0*2) = pack2h(v0, v1);
        }
    }
    __syncthreads();

    float C2[24];
    #pragma unroll
    for (int i = 0; i < 24; i++) C2[i] = 0.f;

    const unsigned a1addr = sb + A1S + (unsigned)((rg*16 + (ln & 15))*400 + (ln >> 4)*16);
    const unsigned a2addr = sb + A2S + (unsigned)((rg*16 + (ln & 15))*144 + (ln >> 4)*16);
    const int brow = ln & 7;
    const int boff = ((ln >> 3) & 3) * 16;

    int p1 = 0, p2 = 0;
    for (int nt = 0; nt < 12; nt++) {
        MBAR_WAIT(sb + MBARS, p1); p1 ^= 1;

        // ---- GEMM1: warp = 16 rows x 16 cols ----
        float C1[8];
        #pragma unroll
        for (int i = 0; i < 8; i++) C1[i] = 0.f;
        for (int p = 0; p < 6; p++) {
            unsigned ah0[4], ah1[4];
            ldsm_x4(ah0, a1addr + p*64);
            ldsm_x4(ah1, a1addr + p*64 + 32);
            unsigned bf[2][4];
            #pragma unroll
            for (int na = 0; na < 2; na++)
                ldsm_x4(bf[na], sb + B1S_ + (unsigned)((nh*16 + na*8 + brow)*400 + p*64 + boff));
            #pragma unroll
            for (int na = 0; na < 2; na++) mma16816(C1 + na*4, ah0, bf[na]);
            #pragma unroll
            for (int na = 0; na < 2; na++) mma16816(C1 + na*4, ah1, bf[na] + 2);
        }

        // ---- epilogue1: bias + relu -> fp16 A2 smem ----
        {
            int rA = rg*16 + g;
            #pragma unroll
            for (int na = 0; na < 2; na++) {
                int kc = nh*16 + na*8 + 2*ti;
                int colT = nt*64 + kc;
                float bb0 = (colT   < Ff) ? __ldg(b1 + colT)     : 0.f;
                float bb1 = (colT+1 < Ff) ? __ldg(b1 + colT + 1) : 0.f;
                *(unsigned*)(sm2 + A2S + rA*144 + kc*2) =
                    pack2h(fmaxf(C1[na*4+0]+bb0, 0.f), fmaxf(C1[na*4+1]+bb1, 0.f));
                *(unsigned*)(sm2 + A2S + (rA+8)*144 + kc*2) =
                    pack2h(fmaxf(C1[na*4+2]+bb0, 0.f), fmaxf(C1[na*4+3]+bb1, 0.f));
            }
        }

        __syncthreads();
        if (nt < 11 && tid == 0) {
            MBAR_EXPECT_TX(sb + MBARS, W1BLK);
            BULK_LD(sb + B1S_, g_W1B + (size_t)(nt+1)*W1BLK, W1BLK, sb + MBARS);
        }

        MBAR_WAIT(sb + MBARS + 8, p2); p2 ^= 1;

        // ---- GEMM2: warp = 16 rows x 48 cols ----
        for (int p = 0; p < 2; p++) {
            unsigned ah0[4], ah1[4];
            ldsm_x4(ah0, a2addr + p*64);
            ldsm_x4(ah1, a2addr + p*64 + 32);
            #pragma unroll
            for (int grp = 0; grp < 3; grp++) {
                unsigned bf[2][4];
                #pragma unroll
                for (int j = 0; j < 2; j++)
                    ldsm_x4(bf[j], sb + B2S_ + (unsigned)((nh*48 + (grp*2+j)*8 + brow)*144 + p*64 + boff));
                float* Cg = C2 + grp*8;
                #pragma unroll
                for (int j = 0; j < 2; j++) mma16816(Cg + j*4, ah0, bf[j]);
                #pragma unroll
                for (int j = 0; j < 2; j++) mma16816(Cg + j*4, ah1, bf[j] + 2);
            }
        }
        __syncthreads();
        if (nt < 11 && tid == 0) {
            MBAR_EXPECT_TX(sb + MBARS + 8, W2BLK);
            BULK_LD(sb + B2S_, g_W2B + (size_t)(nt+1)*W2BLK, W2BLK, sb + MBARS + 8);
        }
    }

    // ---- final: C2 + b2 + residual -> out ----
    {
        size_t rA = row0 + rg*16 + g;
        size_t rB = rA + 8;
        #pragma unroll
        for (int na = 0; na < 6; na++) {
            int col = nh*48 + na*8 + 2*ti;
            if (col < Cc) {
                float b20 = __ldg(b2 + col), b21 = __ldg(b2 + col + 1);
                out[rA*Cc + col]     = C2[na*4+0] + b20 + g_X2[rA*Cc + col];
                out[rA*Cc + col + 1] = C2[na*4+1] + b21 + g_X2[rA*Cc + col + 1];
                out[rB*Cc + col]     = C2[na*4+2] + b20 + g_X2[rB*Cc + col];
                out[rB*Cc + col + 1] = C2[na*4+3] + b21 + g_X2[rB*Cc + col + 1];
            }
        }
    }
}

// ============================================================================
// Launch
// ============================================================================
extern "C" void kernel_launch(void* const* d_in, const int* in_sizes, int n_in,
                              void* d_out, int out_size) {
    const float* x   = (const float*)d_in[0];
    const float* wq  = (const float*)d_in[1];
    const float* wk  = (const float*)d_in[2];
    const float* wv  = (const float*)d_in[3];
    const float* g1  = (const float*)d_in[4];
    const float* be1 = (const float*)d_in[5];
    const float* g2  = (const float*)d_in[6];
    const float* be2 = (const float*)d_in[7];
    const float* w1  = (const float*)d_in[8];
    const float* b1  = (const float*)d_in[9];
    const float* w2  = (const float*)d_in[10];
    const float* b2  = (const float*)d_in[11];
    float* out = (float*)d_out;

    cudaFuncSetAttribute(ln1qkv_kernel, cudaFuncAttributeMaxDynamicSharedMemorySize, SMQ_TOTAL);
    cudaFuncSetAttribute(attn2_kernel, cudaFuncAttributeMaxDynamicSharedMemorySize,
                         SMH_TOTAL * (int)sizeof(float));
    cudaFuncSetAttribute(mlp_kernel, cudaFuncAttributeMaxDynamicSharedMemorySize, SM2_TOTAL);

    prep_all<<<148, 256>>>(wq, wk, wv, w1, w2);
    ln1qkv_kernel<<<ROWS / 32, NTK, SMQ_TOTAL>>>(x, g1, be1);
    dim3 agrid(Bb, 3);
    attn2_kernel<<<agrid, 64, SMH_TOTAL * sizeof(float)>>>(x);
    mlp_kernel<<<ROWS / 32, NTK, SM2_TOTAL>>>(g2, be2, b1, b2, out);
}